// round 14
// baseline (speedup 1.0000x reference)
#include <cuda_runtime.h>
#include <cuda_fp16.h>
#include <math.h>
#include <stdint.h>

// ---------------- problem constants ----------------
#define B_SZ    512
#define LEAVES  256
#define HIDDEN  300
#define VOCAB   50000
#define P       320                  // padded feature pitch (fp16 elements)
#define EPITCH  304                  // embedding fp16 pitch (608B, 16B-aligned)
#define M0      (B_SZ * 2 * LEAVES)  // 262144 leaf rows
#define KP_LEAF 304                  // 19 chunks
#define KP_H    640                  // 40 chunks (2 all-zero, skipped -> 38)

// ---------------- GEMM tiling ----------------
#define BM     64
#define BN     160       // per-CTA N (2 CTAs cover 320)
#define BK     16
#define NSTAGE 6         // ring, loads issued at distance 4/5
// compact layout: 32B row pitch (8 u32), XOR swizzle on 16B granule
#define ATILE_B   2048                   // 64 rows * 32B
#define BTILE_B   5120                   // 160 rows * 32B
#define CHUNK_U32 2560                   // full-320-row packed chunk (320*8 u32)
#define OFF_B_BASE (NSTAGE * ATILE_B)    // 12288
#define SMEM_TOT (NSTAGE * (ATILE_B + BTILE_B))   // 43008 B

// ---------------- device scratch ----------------
__device__ __align__(16) __half g_bufA[(size_t)M0 * P];
__device__ __align__(16) __half g_bufB[(size_t)(M0 / 2) * P];
__device__ __align__(16) __half g_embH[(size_t)VOCAB * EPITCH];
__device__ __align__(16) uint32_t g_BleafP[(KP_LEAF / BK) * CHUNK_U32];
__device__ __align__(16) uint32_t g_BhP[(KP_H / BK) * CHUNK_U32];
__device__ __align__(16) float g_bias[P];

// ---------------- PTX helpers ----------------
__device__ __forceinline__ uint32_t s2u(const void* p) {
    uint32_t a;
    asm("{.reg .u64 t; cvta.to.shared.u64 t, %1; cvt.u32.u64 %0, t;}" : "=r"(a) : "l"(p));
    return a;
}
__device__ __forceinline__ void cpa16(uint32_t dst, const void* src) {
    asm volatile("cp.async.cg.shared.global [%0], [%1], 16;\n" :: "r"(dst), "l"(src));
}
__device__ __forceinline__ void cpa_commit() { asm volatile("cp.async.commit_group;\n"); }
template <int N> __device__ __forceinline__ void cpa_wait() {
    asm volatile("cp.async.wait_group %0;\n" :: "n"(N));
}
__device__ __forceinline__ void ldsm4(uint32_t* r, uint32_t addr) {
    asm volatile("ldmatrix.sync.aligned.m8n8.x4.shared.b16 {%0,%1,%2,%3}, [%4];"
                 : "=r"(r[0]), "=r"(r[1]), "=r"(r[2]), "=r"(r[3]) : "r"(addr));
}
__device__ __forceinline__ void ldsm2(uint32_t* r, uint32_t addr) {
    asm volatile("ldmatrix.sync.aligned.m8n8.x2.shared.b16 {%0,%1}, [%2];"
                 : "=r"(r[0]), "=r"(r[1]) : "r"(addr));
}
__device__ __forceinline__ void mma_f16(float* d, const uint32_t* a, uint32_t b0, uint32_t b1) {
    asm volatile(
        "mma.sync.aligned.m16n8k16.row.col.f32.f16.f16.f32 "
        "{%0,%1,%2,%3}, {%4,%5,%6,%7}, {%8,%9}, {%0,%1,%2,%3};"
        : "+f"(d[0]), "+f"(d[1]), "+f"(d[2]), "+f"(d[3])
        : "r"(a[0]), "r"(a[1]), "r"(a[2]), "r"(a[3]), "r"(b0), "r"(b1));
}

// ---------------- prep kernels ----------------
__global__ void prep_embH(const float* __restrict__ e, __half* __restrict__ o, int n) {
    int i = blockIdx.x * blockDim.x + threadIdx.x;
    if (i >= n) return;
    int row = i / EPITCH, col = i % EPITCH;
    o[i] = __float2half_rn(col < HIDDEN ? e[row * HIDDEN + col] : 0.f);
}

// Packed B image per BK16 chunk: row n (8 u32 = 32B); storage granule gs holds
// logical g = gs ^ ((n>>2)&1); u32 w -> k = 16*kt + g*8 + w*2
#define TL_LEAF ((KP_LEAF / BK) * CHUNK_U32)   // 48640
#define TL_TREE ((KP_H / BK) * CHUNK_U32)      // 102400
__global__ void prep_weights(const float* __restrict__ Wl, const float* __restrict__ Wh,
                             const float* __restrict__ bh) {
    int e = blockIdx.x * blockDim.x + threadIdx.x;
    if (e < TL_LEAF) {
        int kt = e / CHUNK_U32, rme = e % CHUNK_U32;
        int n = rme >> 3, q = rme & 7;
        int g = (q >> 2) ^ ((n >> 2) & 1);
        int k = kt * BK + g * 8 + (q & 3) * 2;
        float v0 = 0.f, v1 = 0.f;
        if (n < HIDDEN && k < HIDDEN)     v0 = Wl[n * HIDDEN + k];
        if (n < HIDDEN && k + 1 < HIDDEN) v1 = Wl[n * HIDDEN + k + 1];
        __half2 h = __floats2half2_rn(v0, v1);
        g_BleafP[e] = *reinterpret_cast<uint32_t*>(&h);
        return;
    }
    e -= TL_LEAF;
    if (e < TL_TREE) {
        int kt = e / CHUNK_U32, rme = e % CHUNK_U32;
        int n = rme >> 3, q = rme & 7;
        int g = (q >> 2) ^ ((n >> 2) & 1);
        int kg = kt * BK + g * 8 + (q & 3) * 2;
        int half = (kg >= P) ? 1 : 0;
        int kk = kg - half * P;
        float v0 = 0.f, v1 = 0.f;
        if (n < HIDDEN && kk < HIDDEN)     v0 = Wh[n * (2 * HIDDEN) + half * HIDDEN + kk];
        if (n < HIDDEN && kk + 1 < HIDDEN) v1 = Wh[n * (2 * HIDDEN) + half * HIDDEN + kk + 1];
        __half2 h = __floats2half2_rn(v0, v1);
        g_BhP[e] = *reinterpret_cast<uint32_t*>(&h);
        return;
    }
    e -= TL_TREE;
    if (e < P) g_bias[e] = (e < HIDDEN) ? bh[e] : 0.f;
}

// ---------------- fp16 mma.sync GEMM (compile-time K loop, paired, SOUND) ----
// grid = (M/64, 2); 128 thr; warp grid 1(M) x 4(N); warp tile 64 x 40.
// One wait+barrier per PAIR: at pair top, chunks kt,kt+1 are complete
// (wait<2>) and visible to all warps (barrier); both LDFRAGs follow the
// barrier. Loads in pair kt overwrite stages whose fragments were read in
// pair kt-2 — every read->overwrite crosses the pair-kt barrier.
template <bool GATHER, bool BIAS, int KT, bool SKIP>
__global__ __launch_bounds__(128, 3)
void gemm_f16(const __half* __restrict__ A, const int* __restrict__ ids,
              const uint32_t* __restrict__ Bp, const float* __restrict__ bias,
              __half* __restrict__ C, int Kp) {
    extern __shared__ uint32_t smem[];
    const uint32_t sb = s2u(smem);
    const int t = threadIdx.x;
    const int wid = t >> 5, lane = t & 31;
    const int m0 = blockIdx.x * BM;
    const int nb = blockIdx.y * BN;

    // A loader: row lm = t>>1, granule lg = t&1 (16B), swizzled store
    const int lm = t >> 1, lg = t & 1;
    const __half* arow;
    if (GATHER) arow = A + (size_t)ids[m0 + lm] * EPITCH;
    else        arow = A + (size_t)(m0 + lm) * Kp;
    const uint32_t aDstOff = (uint32_t)(lm * 32 + ((lg ^ ((lm >> 2) & 1)) << 4));

    const uint32_t bDstBase = sb + OFF_B_BASE;
    const uint32_t bSrcRow  = (uint32_t)nb * 8;

    const int l = lane;
    const int rowA = (l & 7) + ((l >> 3) & 1) * 8;
    const uint32_t laneoffA = (uint32_t)(rowA * 32 + ((((l >> 4) & 1) ^ ((rowA >> 2) & 1)) << 4));
    const int rowB = (l & 7) + ((l >> 4) & 1) * 8;
    const uint32_t laneoffB = (uint32_t)(rowB * 32 + ((((l >> 3) & 1) ^ ((rowB >> 2) & 1)) << 4));
    const int rowB2 = l & 7;
    const uint32_t laneoffB2 = (uint32_t)(rowB2 * 32 + ((((l >> 3) & 1) ^ ((rowB2 >> 2) & 1)) << 4));
    const uint32_t wB = (uint32_t)(wid * 40 * 32);

    float acc[4][5][4];
#pragma unroll
    for (int mt = 0; mt < 4; mt++)
#pragma unroll
        for (int nt = 0; nt < 5; nt++)
#pragma unroll
            for (int q = 0; q < 4; q++) acc[mt][nt][q] = 0.f;

    uint32_t fa[2][4][4], fb[2][10];

#define MAPKT(kt)  (SKIP ? ((kt) + ((kt) >= 19)) : (kt))
#define LOAD_AB(s, ktm)                                                          \
    do {                                                                         \
        cpa16(sb + (s) * ATILE_B + aDstOff, arow + (ktm) * BK + lg * 8);         \
        const uint32_t* _bsrc = Bp + (size_t)(ktm) * CHUNK_U32 + bSrcRow;        \
        uint32_t _bdst = bDstBase + (s) * BTILE_B;                               \
        cpa16(_bdst + t * 16, _bsrc + t * 4);                                    \
        cpa16(_bdst + (t + 128) * 16, _bsrc + (t + 128) * 4);                    \
        if (t < 64) cpa16(_bdst + (t + 256) * 16, _bsrc + (t + 256) * 4);        \
    } while (0)
#define LDFRAG(buf, s)                                                           \
    do {                                                                         \
        const uint32_t _sA = sb + (s) * ATILE_B;                                 \
        const uint32_t _sB = bDstBase + (s) * BTILE_B + wB;                      \
        ldsm4(fa[buf][0], _sA + 0 * 512 + laneoffA);                             \
        ldsm4(fa[buf][1], _sA + 1 * 512 + laneoffA);                             \
        ldsm4(fa[buf][2], _sA + 2 * 512 + laneoffA);                             \
        ldsm4(fa[buf][3], _sA + 3 * 512 + laneoffA);                             \
        ldsm4(&fb[buf][0], _sB + laneoffB);                                      \
        ldsm4(&fb[buf][4], _sB + 512 + laneoffB);                                \
        ldsm2(&fb[buf][8], _sB + 1024 + laneoffB2);                              \
    } while (0)
#define COMPUTE(buf)                                                             \
    do {                                                                         \
        _Pragma("unroll")                                                        \
        for (int mt = 0; mt < 4; mt++) {                                         \
            mma_f16(acc[mt][0], fa[buf][mt], fb[buf][0], fb[buf][1]);            \
            mma_f16(acc[mt][1], fa[buf][mt], fb[buf][2], fb[buf][3]);            \
            mma_f16(acc[mt][2], fa[buf][mt], fb[buf][4], fb[buf][5]);            \
            mma_f16(acc[mt][3], fa[buf][mt], fb[buf][6], fb[buf][7]);            \
            mma_f16(acc[mt][4], fa[buf][mt], fb[buf][8], fb[buf][9]);            \
        }                                                                        \
    } while (0)

    // prologue: chunks 0..3 (one commit group per chunk)
#pragma unroll
    for (int s = 0; s < 4; s++) { LOAD_AB(s, MAPKT(s)); cpa_commit(); }

    // main loop: pairs of chunks, ONE wait + ONE barrier per pair
#pragma unroll
    for (int kt = 0; kt < KT; kt += 2) {
        cpa_wait<2>();          // own groups for chunks kt, kt+1 complete
        __syncthreads();        // all warps' copies visible; all past pair kt-2 LDFRAGs

        LDFRAG(0, kt % NSTAGE);
        if (kt + 1 < KT) LDFRAG(1, (kt + 1) % NSTAGE);

        // refills: stages (kt+4)%6 = (kt-2)%6 and (kt+5)%6 = (kt-1)%6, both
        // read in pair kt-2 -> safely behind this pair's barrier
        if (kt + 4 < KT) { LOAD_AB((kt + 4) % NSTAGE, MAPKT(kt + 4)); }
        cpa_commit();
        if (kt + 5 < KT) { LOAD_AB((kt + 5) % NSTAGE, MAPKT(kt + 5)); }
        cpa_commit();

        COMPUTE(0);
        if (kt + 1 < KT) COMPUTE(1);
    }

    // epilogue
    const int r = lane >> 2, c = lane & 3;
#pragma unroll
    for (int mt = 0; mt < 4; mt++) {
        int row = m0 + mt * 16 + r;
#pragma unroll
        for (int nt = 0; nt < 5; nt++) {
            int col = nb + wid * 40 + nt * 8 + 2 * c;
            float v0 = acc[mt][nt][0], v1 = acc[mt][nt][1];
            float v2 = acc[mt][nt][2], v3 = acc[mt][nt][3];
            if (BIAS) {
                float b0 = __ldg(bias + col), b1 = __ldg(bias + col + 1);
                v0 += b0; v1 += b1; v2 += b0; v3 += b1;
            }
            __half2 h0 = __floats2half2_rn(v0, v1);
            __half2 h1 = __floats2half2_rn(v2, v3);
            *reinterpret_cast<__half2*>(&C[(size_t)row * P + col])       = h0;
            *reinterpret_cast<__half2*>(&C[(size_t)(row + 8) * P + col]) = h1;
        }
    }
#undef MAPKT
#undef LOAD_AB
#undef LDFRAG
#undef COMPUTE
}

// ---------------- classifier ----------------
__global__ void classifier_kernel(const __half* __restrict__ roots,
                                  const float* __restrict__ Wc,
                                  const float* __restrict__ bc,
                                  float* __restrict__ out) {
    const int b = blockIdx.x;
    const __half* base = roots + (size_t)(2 * b) * P;
    float p0 = 0.f, p1 = 0.f, p2 = 0.f;
    for (int j = threadIdx.x; j < 2 * HIDDEN; j += blockDim.x) {
        int off = (j < HIDDEN) ? j : (j + (P - HIDDEN));
        float v = 1.f / (1.f + expf(-__half2float(base[off])));
        p0 += v * Wc[j];
        p1 += v * Wc[2 * HIDDEN + j];
        p2 += v * Wc[4 * HIDDEN + j];
    }
#pragma unroll
    for (int o = 16; o; o >>= 1) {
        p0 += __shfl_down_sync(0xffffffffu, p0, o);
        p1 += __shfl_down_sync(0xffffffffu, p1, o);
        p2 += __shfl_down_sync(0xffffffffu, p2, o);
    }
    __shared__ float red[3][4];
    int warp = threadIdx.x >> 5, lane = threadIdx.x & 31;
    if (lane == 0) { red[0][warp] = p0; red[1][warp] = p1; red[2][warp] = p2; }
    __syncthreads();
    if (threadIdx.x == 0) {
        float l0 = bc[0], l1 = bc[1], l2 = bc[2];
        int nw = blockDim.x >> 5;
        for (int w = 0; w < nw; w++) { l0 += red[0][w]; l1 += red[1][w]; l2 += red[2][w]; }
        float m = fmaxf(l0, fmaxf(l1, l2));
        float s = expf(l0 - m) + expf(l1 - m) + expf(l2 - m);
        float lse = m + logf(s);
        out[b * 3 + 0] = l0 - lse;
        out[b * 3 + 1] = l1 - lse;
        out[b * 3 + 2] = l2 - lse;
    }
}

// ---------------- kernel_launch ----------------
extern "C" void kernel_launch(void* const* d_in, const int* in_sizes, int n_in,
                              void* d_out, int out_size) {
    const int*   word_ids  = (const int*)d_in[0];
    const float* embedding = (const float*)d_in[1];
    const float* W_leaf    = (const float*)d_in[2];
    const float* W_h       = (const float*)d_in[3];
    const float* b_h       = (const float*)d_in[4];
    const float* W_cls     = (const float*)d_in[5];
    const float* b_cls     = (const float*)d_in[6];
    float* out = (float*)d_out;

    __half *bufA, *bufB, *embH;
    uint32_t *bleaf, *bh;
    float *bias;
    cudaGetSymbolAddress((void**)&bufA, g_bufA);
    cudaGetSymbolAddress((void**)&bufB, g_bufB);
    cudaGetSymbolAddress((void**)&embH, g_embH);
    cudaGetSymbolAddress((void**)&bleaf, g_BleafP);
    cudaGetSymbolAddress((void**)&bh, g_BhP);
    cudaGetSymbolAddress((void**)&bias, g_bias);

    static bool attr_done = false;
    if (!attr_done) {
        cudaFuncSetAttribute(gemm_f16<true, false, 19, false>,
                             cudaFuncAttributeMaxDynamicSharedMemorySize, SMEM_TOT);
        cudaFuncSetAttribute(gemm_f16<false, true, 38, true>,
                             cudaFuncAttributeMaxDynamicSharedMemorySize, SMEM_TOT);
        attr_done = true;
    }

    {
        int n = VOCAB * EPITCH;
        prep_embH<<<(n + 255) / 256, 256>>>(embedding, embH, n);
        int tw = TL_LEAF + TL_TREE + P;
        prep_weights<<<(tw + 255) / 256, 256>>>(W_leaf, W_h, b_h);
    }

    // leaf: H0[262144, 320] = fp16(emb[ids]) @ Bleaf  (K = 304, KT = 19)
    {
        dim3 grid(M0 / BM, 2);
        gemm_f16<true, false, 19, false><<<grid, 128, SMEM_TOT>>>(embH, word_ids, bleaf, nullptr,
                                                                  bufA, KP_LEAF);
    }

    // tree levels: view [2M, 320] as [M, 640]; KT = 38 (zero chunks skipped)
    __half* cur = bufA;
    int M = M0;
    for (int lvl = 0; lvl < 8; lvl++) {
        M >>= 1;
        __half* nxt = (cur == bufA) ? bufB : bufA;
        dim3 grid(M / BM, 2);
        gemm_f16<false, true, 38, true><<<grid, 128, SMEM_TOT>>>(cur, nullptr, bh, bias, nxt, KP_H);
        cur = nxt;
    }

    classifier_kernel<<<B_SZ, 128>>>(cur, W_cls, b_cls, out);
    (void)in_sizes; (void)n_in; (void)out_size;
}

// round 15
// speedup vs baseline: 1.4506x; 1.4506x over previous
#include <cuda_runtime.h>
#include <cuda_fp16.h>
#include <math.h>
#include <stdint.h>

// ---------------- problem constants ----------------
#define B_SZ    512
#define LEAVES  256
#define HIDDEN  300
#define VOCAB   50000
#define P       320                  // padded feature pitch (fp16 elements)
#define EPITCH  304                  // embedding fp16 pitch (608B, 16B-aligned)
#define M0      (B_SZ * 2 * LEAVES)  // 262144 leaf rows
#define KP_LEAF 304                  // 19 chunks
#define KP_H    640                  // 40 chunks (2 all-zero, skipped -> 38)

// ---------------- GEMM tiling ----------------
#define BM     64
#define BN     152       // per-CTA computed N cols (2 CTAs cover 304; 304..319 dead)
#define BK     16
#define NSTAGE 6
// compact layout: 32B row pitch (8 u32), XOR swizzle on 16B granule
#define ATILE_B   2048                   // 64 rows * 32B
#define BTILE_B   4864                   // 152 rows * 32B
#define CHUNK_U32 2432                   // packed chunk: 304 rows * 8 u32
#define OFF_B_BASE (NSTAGE * ATILE_B)    // 12288
#define SMEM_TOT (NSTAGE * (ATILE_B + BTILE_B))   // 41472 B

// ---------------- device scratch ----------------
__device__ __align__(16) __half g_bufA[(size_t)M0 * P];
__device__ __align__(16) __half g_bufB[(size_t)(M0 / 2) * P];
__device__ __align__(16) __half g_embH[(size_t)VOCAB * EPITCH];
__device__ __align__(16) uint32_t g_BleafP[(KP_LEAF / BK) * CHUNK_U32];
__device__ __align__(16) uint32_t g_BhP[(KP_H / BK) * CHUNK_U32];
__device__ __align__(16) float g_bias[P];

// ---------------- PTX helpers ----------------
__device__ __forceinline__ uint32_t s2u(const void* p) {
    uint32_t a;
    asm("{.reg .u64 t; cvta.to.shared.u64 t, %1; cvt.u32.u64 %0, t;}" : "=r"(a) : "l"(p));
    return a;
}
__device__ __forceinline__ void cpa16(uint32_t dst, const void* src) {
    asm volatile("cp.async.cg.shared.global [%0], [%1], 16;\n" :: "r"(dst), "l"(src));
}
__device__ __forceinline__ void cpa_commit() { asm volatile("cp.async.commit_group;\n"); }
template <int N> __device__ __forceinline__ void cpa_wait() {
    asm volatile("cp.async.wait_group %0;\n" :: "n"(N));
}
__device__ __forceinline__ void ldsm4(uint32_t* r, uint32_t addr) {
    asm volatile("ldmatrix.sync.aligned.m8n8.x4.shared.b16 {%0,%1,%2,%3}, [%4];"
                 : "=r"(r[0]), "=r"(r[1]), "=r"(r[2]), "=r"(r[3]) : "r"(addr));
}
__device__ __forceinline__ void ldsm2(uint32_t* r, uint32_t addr) {
    asm volatile("ldmatrix.sync.aligned.m8n8.x2.shared.b16 {%0,%1}, [%2];"
                 : "=r"(r[0]), "=r"(r[1]) : "r"(addr));
}
__device__ __forceinline__ void mma_f16(float* d, const uint32_t* a, uint32_t b0, uint32_t b1) {
    asm volatile(
        "mma.sync.aligned.m16n8k16.row.col.f32.f16.f16.f32 "
        "{%0,%1,%2,%3}, {%4,%5,%6,%7}, {%8,%9}, {%0,%1,%2,%3};"
        : "+f"(d[0]), "+f"(d[1]), "+f"(d[2]), "+f"(d[3])
        : "r"(a[0]), "r"(a[1]), "r"(a[2]), "r"(a[3]), "r"(b0), "r"(b1));
}

// ---------------- merged prep kernel ----------------
// Packed B image per BK16 chunk: 304 rows x 8 u32; storage granule gs holds
// logical g = gs ^ ((n>>2)&1); u32 w -> k = 16*kt + g*8 + w*2
#define NE_EMB  (VOCAB * EPITCH)               // 15200000
#define TL_LEAF ((KP_LEAF / BK) * CHUNK_U32)   // 46208
#define TL_TREE ((KP_H / BK) * CHUNK_U32)      // 97280
#define PREP_TOT (NE_EMB + TL_LEAF + TL_TREE + P)
__global__ void prep_all(const float* __restrict__ emb, const float* __restrict__ Wl,
                         const float* __restrict__ Wh, const float* __restrict__ bh) {
    int e = blockIdx.x * blockDim.x + threadIdx.x;
    if (e < NE_EMB) {
        int row = e / EPITCH, col = e % EPITCH;
        g_embH[e] = __float2half_rn(col < HIDDEN ? emb[row * HIDDEN + col] : 0.f);
        return;
    }
    e -= NE_EMB;
    if (e < TL_LEAF) {
        int kt = e / CHUNK_U32, rme = e % CHUNK_U32;
        int n = rme >> 3, q = rme & 7;
        int g = (q >> 2) ^ ((n >> 2) & 1);
        int k = kt * BK + g * 8 + (q & 3) * 2;
        float v0 = 0.f, v1 = 0.f;
        if (n < HIDDEN && k < HIDDEN)     v0 = Wl[n * HIDDEN + k];
        if (n < HIDDEN && k + 1 < HIDDEN) v1 = Wl[n * HIDDEN + k + 1];
        __half2 h = __floats2half2_rn(v0, v1);
        g_BleafP[e] = *reinterpret_cast<uint32_t*>(&h);
        return;
    }
    e -= TL_LEAF;
    if (e < TL_TREE) {
        int kt = e / CHUNK_U32, rme = e % CHUNK_U32;
        int n = rme >> 3, q = rme & 7;
        int g = (q >> 2) ^ ((n >> 2) & 1);
        int kg = kt * BK + g * 8 + (q & 3) * 2;
        int half = (kg >= P) ? 1 : 0;
        int kk = kg - half * P;
        float v0 = 0.f, v1 = 0.f;
        if (n < HIDDEN && kk < HIDDEN)     v0 = Wh[n * (2 * HIDDEN) + half * HIDDEN + kk];
        if (n < HIDDEN && kk + 1 < HIDDEN) v1 = Wh[n * (2 * HIDDEN) + half * HIDDEN + kk + 1];
        __half2 h = __floats2half2_rn(v0, v1);
        g_BhP[e] = *reinterpret_cast<uint32_t*>(&h);
        return;
    }
    e -= TL_TREE;
    if (e < P) g_bias[e] = (e < HIDDEN) ? bh[e] : 0.f;
}

// ---------------- fp16 mma.sync GEMM (R12 structure, N=304 trim) ----------
// grid = (M/64, 2); 128 thr; warp grid 1(M) x 4(N); warp tiles {40,40,40,32}.
// Per-chunk wait+barrier; LDFRAG(kt+1) issued before COMPUTE(kt) for overlap.
template <bool GATHER, bool BIAS, int KT, bool SKIP>
__global__ __launch_bounds__(128, 3)
void gemm_f16(const __half* __restrict__ A, const int* __restrict__ ids,
              const uint32_t* __restrict__ Bp, const float* __restrict__ bias,
              __half* __restrict__ C, int Kp) {
    extern __shared__ uint32_t smem[];
    const uint32_t sb = s2u(smem);
    const int t = threadIdx.x;
    const int wid = t >> 5, lane = t & 31;
    const int m0 = blockIdx.x * BM;
    const int nb = blockIdx.y * BN;

    // A loader: row lm = t>>1, granule lg = t&1 (16B), swizzled store
    const int lm = t >> 1, lg = t & 1;
    const __half* arow;
    if (GATHER) arow = A + (size_t)ids[m0 + lm] * EPITCH;
    else        arow = A + (size_t)(m0 + lm) * Kp;
    const uint32_t aDstOff = (uint32_t)(lm * 32 + ((lg ^ ((lm >> 2) & 1)) << 4));

    const uint32_t bDstBase = sb + OFF_B_BASE;
    const uint32_t bSrcRow  = (uint32_t)nb * 8;

    const int l = lane;
    const int rowA = (l & 7) + ((l >> 3) & 1) * 8;
    const uint32_t laneoffA = (uint32_t)(rowA * 32 + ((((l >> 4) & 1) ^ ((rowA >> 2) & 1)) << 4));
    const int rowB = (l & 7) + ((l >> 4) & 1) * 8;
    const uint32_t laneoffB = (uint32_t)(rowB * 32 + ((((l >> 3) & 1) ^ ((rowB >> 2) & 1)) << 4));
    const int rowB2 = l & 7;
    const uint32_t laneoffB2 = (uint32_t)(rowB2 * 32 + ((((l >> 3) & 1) ^ ((rowB2 >> 2) & 1)) << 4));
    const uint32_t wB = (uint32_t)(wid * 40 * 32);   // warp slab base (warp3: rows 120..151)
    const bool fullWarp = (wid < 3);                 // warp3 has 32 cols (no ldsm2 tile)

    float acc[4][5][4];
#pragma unroll
    for (int mt = 0; mt < 4; mt++)
#pragma unroll
        for (int nt = 0; nt < 5; nt++)
#pragma unroll
            for (int q = 0; q < 4; q++) acc[mt][nt][q] = 0.f;

    uint32_t fa[2][4][4], fb[2][10];

#define MAPKT(kt)  (SKIP ? ((kt) + ((kt) >= 19)) : (kt))
#define LOAD_AB(s, ktm)                                                          \
    do {                                                                         \
        cpa16(sb + (s) * ATILE_B + aDstOff, arow + (ktm) * BK + lg * 8);         \
        const uint32_t* _bsrc = Bp + (size_t)(ktm) * CHUNK_U32 + bSrcRow;        \
        uint32_t _bdst = bDstBase + (s) * BTILE_B;                               \
        cpa16(_bdst + t * 16, _bsrc + t * 4);                                    \
        cpa16(_bdst + (t + 128) * 16, _bsrc + (t + 128) * 4);                    \
        if (t < 48) cpa16(_bdst + (t + 256) * 16, _bsrc + (t + 256) * 4);        \
    } while (0)
#define LDFRAG(buf, s)                                                           \
    do {                                                                         \
        const uint32_t _sA = sb + (s) * ATILE_B;                                 \
        const uint32_t _sB = bDstBase + (s) * BTILE_B + wB;                      \
        ldsm4(fa[buf][0], _sA + 0 * 512 + laneoffA);                             \
        ldsm4(fa[buf][1], _sA + 1 * 512 + laneoffA);                             \
        ldsm4(fa[buf][2], _sA + 2 * 512 + laneoffA);                             \
        ldsm4(fa[buf][3], _sA + 3 * 512 + laneoffA);                             \
        ldsm4(&fb[buf][0], _sB + laneoffB);                                      \
        ldsm4(&fb[buf][4], _sB + 512 + laneoffB);                                \
        if (fullWarp) ldsm2(&fb[buf][8], _sB + 1024 + laneoffB2);                \
    } while (0)
#define COMPUTE(buf)                                                             \
    do {                                                                         \
        _Pragma("unroll")                                                        \
        for (int mt = 0; mt < 4; mt++) {                                         \
            mma_f16(acc[mt][0], fa[buf][mt], fb[buf][0], fb[buf][1]);            \
            mma_f16(acc[mt][1], fa[buf][mt], fb[buf][2], fb[buf][3]);            \
            mma_f16(acc[mt][2], fa[buf][mt], fb[buf][4], fb[buf][5]);            \
            mma_f16(acc[mt][3], fa[buf][mt], fb[buf][6], fb[buf][7]);            \
        }                                                                        \
        if (fullWarp) {                                                          \
            _Pragma("unroll")                                                    \
            for (int mt = 0; mt < 4; mt++)                                       \
                mma_f16(acc[mt][4], fa[buf][mt], fb[buf][8], fb[buf][9]);        \
        }                                                                        \
    } while (0)

    // prologue: fill 5 stages (chunks 0..4)
#pragma unroll
    for (int s = 0; s < 5; s++) { LOAD_AB(s, MAPKT(s)); cpa_commit(); }

    cpa_wait<3>();   // chunks 0,1 resident
    __syncthreads();
    LDFRAG(0, 0);    // chunk 0 -> buffer 0

    // main loop: one wait+barrier per chunk; LDFRAG(kt+1) before COMPUTE(kt)
#pragma unroll
    for (int kt = 0; kt < KT; kt++) {
        const int cur = kt & 1, nxt = cur ^ 1;
        if (kt + 5 < KT) { LOAD_AB((kt + 5) % NSTAGE, MAPKT(kt + 5)); }
        cpa_commit();
        if (kt + 1 < KT) {
            cpa_wait<3>();      // chunk kt+1 resident
            __syncthreads();    // visibility + stage-reuse ordering
            LDFRAG(nxt, (kt + 1) % NSTAGE);
        }
        COMPUTE(cur);
    }

    // epilogue
    const int r = lane >> 2, c = lane & 3;
#pragma unroll
    for (int mt = 0; mt < 4; mt++) {
        int row = m0 + mt * 16 + r;
#pragma unroll
        for (int nt = 0; nt < 5; nt++) {
            if (nt == 4 && !fullWarp) continue;
            int col = nb + wid * 40 + nt * 8 + 2 * c;
            float v0 = acc[mt][nt][0], v1 = acc[mt][nt][1];
            float v2 = acc[mt][nt][2], v3 = acc[mt][nt][3];
            if (BIAS) {
                float b0 = __ldg(bias + col), b1 = __ldg(bias + col + 1);
                v0 += b0; v1 += b1; v2 += b0; v3 += b1;
            }
            __half2 h0 = __floats2half2_rn(v0, v1);
            __half2 h1 = __floats2half2_rn(v2, v3);
            *reinterpret_cast<__half2*>(&C[(size_t)row * P + col])       = h0;
            *reinterpret_cast<__half2*>(&C[(size_t)(row + 8) * P + col]) = h1;
        }
    }
#undef MAPKT
#undef LOAD_AB
#undef LDFRAG
#undef COMPUTE
}

// ---------------- classifier ----------------
__global__ void classifier_kernel(const __half* __restrict__ roots,
                                  const float* __restrict__ Wc,
                                  const float* __restrict__ bc,
                                  float* __restrict__ out) {
    const int b = blockIdx.x;
    const __half* base = roots + (size_t)(2 * b) * P;
    float p0 = 0.f, p1 = 0.f, p2 = 0.f;
    for (int j = threadIdx.x; j < 2 * HIDDEN; j += blockDim.x) {
        int off = (j < HIDDEN) ? j : (j + (P - HIDDEN));
        float v = 1.f / (1.f + expf(-__half2float(base[off])));
        p0 += v * Wc[j];
        p1 += v * Wc[2 * HIDDEN + j];
        p2 += v * Wc[4 * HIDDEN + j];
    }
#pragma unroll
    for (int o = 16; o; o >>= 1) {
        p0 += __shfl_down_sync(0xffffffffu, p0, o);
        p1 += __shfl_down_sync(0xffffffffu, p1, o);
        p2 += __shfl_down_sync(0xffffffffu, p2, o);
    }
    __shared__ float red[3][4];
    int warp = threadIdx.x >> 5, lane = threadIdx.x & 31;
    if (lane == 0) { red[0][warp] = p0; red[1][warp] = p1; red[2][warp] = p2; }
    __syncthreads();
    if (threadIdx.x == 0) {
        float l0 = bc[0], l1 = bc[1], l2 = bc[2];
        int nw = blockDim.x >> 5;
        for (int w = 0; w < nw; w++) { l0 += red[0][w]; l1 += red[1][w]; l2 += red[2][w]; }
        float m = fmaxf(l0, fmaxf(l1, l2));
        float s = expf(l0 - m) + expf(l1 - m) + expf(l2 - m);
        float lse = m + logf(s);
        out[b * 3 + 0] = l0 - lse;
        out[b * 3 + 1] = l1 - lse;
        out[b * 3 + 2] = l2 - lse;
    }
}

// ---------------- kernel_launch ----------------
extern "C" void kernel_launch(void* const* d_in, const int* in_sizes, int n_in,
                              void* d_out, int out_size) {
    const int*   word_ids  = (const int*)d_in[0];
    const float* embedding = (const float*)d_in[1];
    const float* W_leaf    = (const float*)d_in[2];
    const float* W_h       = (const float*)d_in[3];
    const float* b_h       = (const float*)d_in[4];
    const float* W_cls     = (const float*)d_in[5];
    const float* b_cls     = (const float*)d_in[6];
    float* out = (float*)d_out;

    __half *bufA, *bufB, *embH;
    uint32_t *bleaf, *bh;
    float *bias;
    cudaGetSymbolAddress((void**)&bufA, g_bufA);
    cudaGetSymbolAddress((void**)&bufB, g_bufB);
    cudaGetSymbolAddress((void**)&embH, g_embH);
    cudaGetSymbolAddress((void**)&bleaf, g_BleafP);
    cudaGetSymbolAddress((void**)&bh, g_BhP);
    cudaGetSymbolAddress((void**)&bias, g_bias);

    static bool attr_done = false;
    if (!attr_done) {
        cudaFuncSetAttribute(gemm_f16<true, false, 19, false>,
                             cudaFuncAttributeMaxDynamicSharedMemorySize, SMEM_TOT);
        cudaFuncSetAttribute(gemm_f16<false, true, 38, true>,
                             cudaFuncAttributeMaxDynamicSharedMemorySize, SMEM_TOT);
        attr_done = true;
    }

    prep_all<<<(PREP_TOT + 255) / 256, 256>>>(embedding, W_leaf, W_h, b_h);

    // leaf: H0[262144, 0..303] = fp16(emb[ids]) @ Bleaf  (K = 304, KT = 19)
    {
        dim3 grid(M0 / BM, 2);
        gemm_f16<true, false, 19, false><<<grid, 128, SMEM_TOT>>>(embH, word_ids, bleaf, nullptr,
                                                                  bufA, KP_LEAF);
    }

    // tree levels: view [2M, 320] as [M, 640]; KT = 38 (zero chunks skipped)
    __half* cur = bufA;
    int M = M0;
    for (int lvl = 0; lvl < 8; lvl++) {
        M >>= 1;
        __half* nxt = (cur == bufA) ? bufB : bufA;
        dim3 grid(M / BM, 2);
        gemm_f16<false, true, 38, true><<<grid, 128, SMEM_TOT>>>(cur, nullptr, bh, bias, nxt, KP_H);
        cur = nxt;
    }

    classifier_kernel<<<B_SZ, 128>>>(cur, W_cls, b_cls, out);
    (void)in_sizes; (void)n_in; (void)out_size;
}

// round 16
// speedup vs baseline: 1.5375x; 1.0599x over previous
#include <cuda_runtime.h>
#include <cuda_fp16.h>
#include <math.h>
#include <stdint.h>

// ---------------- problem constants ----------------
#define B_SZ    512
#define LEAVES  256
#define HIDDEN  300
#define VOCAB   50000
#define P       320                  // padded feature pitch (fp16 elements)
#define EPITCH  304                  // embedding fp16 pitch (608B, 16B-aligned)
#define M0      (B_SZ * 2 * LEAVES)  // 262144 leaf rows
#define KP_LEAF 304                  // 19 chunks
#define KP_H    640                  // 40 chunks (2 all-zero, skipped -> 38)

// ---------------- GEMM tiling (R12 exact) ----------------
#define BM     64
#define BN     160       // per-CTA N (2 CTAs cover 320)
#define BK     16
#define NSTAGE 6         // ring, prefetch distance 5
// compact layout: 32B row pitch (8 u32), XOR swizzle on 16B granule
#define ATILE_B   2048                   // 64 rows * 32B
#define BTILE_B   5120                   // 160 rows * 32B
#define CHUNK_U32 2560                   // full-320-row packed chunk (320*8 u32)
#define OFF_B_BASE (NSTAGE * ATILE_B)    // 12288
#define SMEM_TOT (NSTAGE * (ATILE_B + BTILE_B))   // 43008 B

// ---------------- device scratch ----------------
__device__ __align__(16) __half g_bufA[(size_t)M0 * P];
__device__ __align__(16) __half g_bufB[(size_t)(M0 / 2) * P];
__device__ __align__(16) __half g_embH[(size_t)VOCAB * EPITCH];
__device__ __align__(16) uint32_t g_BleafP[(KP_LEAF / BK) * CHUNK_U32];
__device__ __align__(16) uint32_t g_BhP[(KP_H / BK) * CHUNK_U32];
__device__ __align__(16) float g_bias[P];

// ---------------- PTX helpers ----------------
__device__ __forceinline__ uint32_t s2u(const void* p) {
    uint32_t a;
    asm("{.reg .u64 t; cvta.to.shared.u64 t, %1; cvt.u32.u64 %0, t;}" : "=r"(a) : "l"(p));
    return a;
}
__device__ __forceinline__ void cpa16(uint32_t dst, const void* src) {
    asm volatile("cp.async.cg.shared.global [%0], [%1], 16;\n" :: "r"(dst), "l"(src));
}
__device__ __forceinline__ void cpa_commit() { asm volatile("cp.async.commit_group;\n"); }
template <int N> __device__ __forceinline__ void cpa_wait() {
    asm volatile("cp.async.wait_group %0;\n" :: "n"(N));
}
__device__ __forceinline__ void ldsm4(uint32_t* r, uint32_t addr) {
    asm volatile("ldmatrix.sync.aligned.m8n8.x4.shared.b16 {%0,%1,%2,%3}, [%4];"
                 : "=r"(r[0]), "=r"(r[1]), "=r"(r[2]), "=r"(r[3]) : "r"(addr));
}
__device__ __forceinline__ void ldsm2(uint32_t* r, uint32_t addr) {
    asm volatile("ldmatrix.sync.aligned.m8n8.x2.shared.b16 {%0,%1}, [%2];"
                 : "=r"(r[0]), "=r"(r[1]) : "r"(addr));
}
__device__ __forceinline__ void mma_f16(float* d, const uint32_t* a, uint32_t b0, uint32_t b1) {
    asm volatile(
        "mma.sync.aligned.m16n8k16.row.col.f32.f16.f16.f32 "
        "{%0,%1,%2,%3}, {%4,%5,%6,%7}, {%8,%9}, {%0,%1,%2,%3};"
        : "+f"(d[0]), "+f"(d[1]), "+f"(d[2]), "+f"(d[3])
        : "r"(a[0]), "r"(a[1]), "r"(a[2]), "r"(a[3]), "r"(b0), "r"(b1));
}

// ---------------- merged prep kernel (single launch) ----------------
// Packed B image per BK16 chunk: row n (8 u32 = 32B); storage granule gs holds
// logical g = gs ^ ((n>>2)&1); u32 w -> k = 16*kt + g*8 + w*2
#define NE_EMB  (VOCAB * EPITCH)               // 15200000
#define TL_LEAF ((KP_LEAF / BK) * CHUNK_U32)   // 48640
#define TL_TREE ((KP_H / BK) * CHUNK_U32)      // 102400
#define PREP_TOT (NE_EMB + TL_LEAF + TL_TREE + P)
__global__ void prep_all(const float* __restrict__ emb, const float* __restrict__ Wl,
                         const float* __restrict__ Wh, const float* __restrict__ bh) {
    int e = blockIdx.x * blockDim.x + threadIdx.x;
    if (e < NE_EMB) {
        int row = e / EPITCH, col = e % EPITCH;
        g_embH[e] = __float2half_rn(col < HIDDEN ? emb[row * HIDDEN + col] : 0.f);
        return;
    }
    e -= NE_EMB;
    if (e < TL_LEAF) {
        int kt = e / CHUNK_U32, rme = e % CHUNK_U32;
        int n = rme >> 3, q = rme & 7;
        int g = (q >> 2) ^ ((n >> 2) & 1);
        int k = kt * BK + g * 8 + (q & 3) * 2;
        float v0 = 0.f, v1 = 0.f;
        if (n < HIDDEN && k < HIDDEN)     v0 = Wl[n * HIDDEN + k];
        if (n < HIDDEN && k + 1 < HIDDEN) v1 = Wl[n * HIDDEN + k + 1];
        __half2 h = __floats2half2_rn(v0, v1);
        g_BleafP[e] = *reinterpret_cast<uint32_t*>(&h);
        return;
    }
    e -= TL_LEAF;
    if (e < TL_TREE) {
        int kt = e / CHUNK_U32, rme = e % CHUNK_U32;
        int n = rme >> 3, q = rme & 7;
        int g = (q >> 2) ^ ((n >> 2) & 1);
        int kg = kt * BK + g * 8 + (q & 3) * 2;
        int half = (kg >= P) ? 1 : 0;
        int kk = kg - half * P;
        float v0 = 0.f, v1 = 0.f;
        if (n < HIDDEN && kk < HIDDEN)     v0 = Wh[n * (2 * HIDDEN) + half * HIDDEN + kk];
        if (n < HIDDEN && kk + 1 < HIDDEN) v1 = Wh[n * (2 * HIDDEN) + half * HIDDEN + kk + 1];
        __half2 h = __floats2half2_rn(v0, v1);
        g_BhP[e] = *reinterpret_cast<uint32_t*>(&h);
        return;
    }
    e -= TL_TREE;
    if (e < P) g_bias[e] = (e < HIDDEN) ? bh[e] : 0.f;
}

// ---------------- fp16 mma.sync GEMM (R12 exact) ----------
// grid = (M/64, 2); 128 thr; warp grid 1(M) x 4(N); warp tile 64 x 40.
// Per-chunk wait+barrier; LDFRAG(kt+1) issued before COMPUTE(kt) for overlap.
template <bool GATHER, bool BIAS, int KT, bool SKIP>
__global__ __launch_bounds__(128, 3)
void gemm_f16(const __half* __restrict__ A, const int* __restrict__ ids,
              const uint32_t* __restrict__ Bp, const float* __restrict__ bias,
              __half* __restrict__ C, int Kp) {
    extern __shared__ uint32_t smem[];
    const uint32_t sb = s2u(smem);
    const int t = threadIdx.x;
    const int wid = t >> 5, lane = t & 31;
    const int m0 = blockIdx.x * BM;
    const int nb = blockIdx.y * BN;

    // A loader: row lm = t>>1, granule lg = t&1 (16B), swizzled store
    const int lm = t >> 1, lg = t & 1;
    const __half* arow;
    if (GATHER) arow = A + (size_t)ids[m0 + lm] * EPITCH;
    else        arow = A + (size_t)(m0 + lm) * Kp;
    const uint32_t aDstOff = (uint32_t)(lm * 32 + ((lg ^ ((lm >> 2) & 1)) << 4));

    const uint32_t bDstBase = sb + OFF_B_BASE;
    const uint32_t bSrcRow  = (uint32_t)nb * 8;

    const int l = lane;
    const int rowA = (l & 7) + ((l >> 3) & 1) * 8;
    const uint32_t laneoffA = (uint32_t)(rowA * 32 + ((((l >> 4) & 1) ^ ((rowA >> 2) & 1)) << 4));
    const int rowB = (l & 7) + ((l >> 4) & 1) * 8;
    const uint32_t laneoffB = (uint32_t)(rowB * 32 + ((((l >> 3) & 1) ^ ((rowB >> 2) & 1)) << 4));
    const int rowB2 = l & 7;
    const uint32_t laneoffB2 = (uint32_t)(rowB2 * 32 + ((((l >> 3) & 1) ^ ((rowB2 >> 2) & 1)) << 4));
    const uint32_t wB = (uint32_t)(wid * 40 * 32);

    float acc[4][5][4];
#pragma unroll
    for (int mt = 0; mt < 4; mt++)
#pragma unroll
        for (int nt = 0; nt < 5; nt++)
#pragma unroll
            for (int q = 0; q < 4; q++) acc[mt][nt][q] = 0.f;

    uint32_t fa[2][4][4], fb[2][10];

#define MAPKT(kt)  (SKIP ? ((kt) + ((kt) >= 19)) : (kt))
#define LOAD_AB(s, ktm)                                                          \
    do {                                                                         \
        cpa16(sb + (s) * ATILE_B + aDstOff, arow + (ktm) * BK + lg * 8);         \
        const uint32_t* _bsrc = Bp + (size_t)(ktm) * CHUNK_U32 + bSrcRow;        \
        uint32_t _bdst = bDstBase + (s) * BTILE_B;                               \
        cpa16(_bdst + t * 16, _bsrc + t * 4);                                    \
        cpa16(_bdst + (t + 128) * 16, _bsrc + (t + 128) * 4);                    \
        if (t < 64) cpa16(_bdst + (t + 256) * 16, _bsrc + (t + 256) * 4);        \
    } while (0)
#define LDFRAG(buf, s)                                                           \
    do {                                                                         \
        const uint32_t _sA = sb + (s) * ATILE_B;                                 \
        const uint32_t _sB = bDstBase + (s) * BTILE_B + wB;                      \
        ldsm4(fa[buf][0], _sA + 0 * 512 + laneoffA);                             \
        ldsm4(fa[buf][1], _sA + 1 * 512 + laneoffA);                             \
        ldsm4(fa[buf][2], _sA + 2 * 512 + laneoffA);                             \
        ldsm4(fa[buf][3], _sA + 3 * 512 + laneoffA);                             \
        ldsm4(&fb[buf][0], _sB + laneoffB);                                      \
        ldsm4(&fb[buf][4], _sB + 512 + laneoffB);                                \
        ldsm2(&fb[buf][8], _sB + 1024 + laneoffB2);                              \
    } while (0)
#define COMPUTE(buf)                                                             \
    do {                                                                         \
        _Pragma("unroll")                                                        \
        for (int mt = 0; mt < 4; mt++) {                                         \
            mma_f16(acc[mt][0], fa[buf][mt], fb[buf][0], fb[buf][1]);            \
            mma_f16(acc[mt][1], fa[buf][mt], fb[buf][2], fb[buf][3]);            \
            mma_f16(acc[mt][2], fa[buf][mt], fb[buf][4], fb[buf][5]);            \
            mma_f16(acc[mt][3], fa[buf][mt], fb[buf][6], fb[buf][7]);            \
            mma_f16(acc[mt][4], fa[buf][mt], fb[buf][8], fb[buf][9]);            \
        }                                                                        \
    } while (0)

    // prologue: fill 5 stages (chunks 0..4)
#pragma unroll
    for (int s = 0; s < 5; s++) { LOAD_AB(s, MAPKT(s)); cpa_commit(); }

    cpa_wait<3>();   // chunks 0,1 resident
    __syncthreads();
    LDFRAG(0, 0);    // chunk 0 -> buffer 0

    // main loop: one wait+barrier per chunk; LDFRAG(kt+1) before COMPUTE(kt)
#pragma unroll
    for (int kt = 0; kt < KT; kt++) {
        const int cur = kt & 1, nxt = cur ^ 1;
        if (kt + 5 < KT) { LOAD_AB((kt + 5) % NSTAGE, MAPKT(kt + 5)); }
        cpa_commit();
        if (kt + 1 < KT) {
            cpa_wait<3>();      // chunk kt+1 resident
            __syncthreads();    // visibility + stage-reuse ordering
            LDFRAG(nxt, (kt + 1) % NSTAGE);
        }
        COMPUTE(cur);
    }

    // epilogue
    const int r = lane >> 2, c = lane & 3;
#pragma unroll
    for (int mt = 0; mt < 4; mt++) {
        int row = m0 + mt * 16 + r;
#pragma unroll
        for (int nt = 0; nt < 5; nt++) {
            int col = nb + wid * 40 + nt * 8 + 2 * c;
            float v0 = acc[mt][nt][0], v1 = acc[mt][nt][1];
            float v2 = acc[mt][nt][2], v3 = acc[mt][nt][3];
            if (BIAS) {
                float b0 = __ldg(bias + col), b1 = __ldg(bias + col + 1);
                v0 += b0; v1 += b1; v2 += b0; v3 += b1;
            }
            __half2 h0 = __floats2half2_rn(v0, v1);
            __half2 h1 = __floats2half2_rn(v2, v3);
            *reinterpret_cast<__half2*>(&C[(size_t)row * P + col])       = h0;
            *reinterpret_cast<__half2*>(&C[(size_t)(row + 8) * P + col]) = h1;
        }
    }
#undef MAPKT
#undef LOAD_AB
#undef LDFRAG
#undef COMPUTE
}

// ---------------- classifier ----------------
__global__ void classifier_kernel(const __half* __restrict__ roots,
                                  const float* __restrict__ Wc,
                                  const float* __restrict__ bc,
                                  float* __restrict__ out) {
    const int b = blockIdx.x;
    const __half* base = roots + (size_t)(2 * b) * P;
    float p0 = 0.f, p1 = 0.f, p2 = 0.f;
    for (int j = threadIdx.x; j < 2 * HIDDEN; j += blockDim.x) {
        int off = (j < HIDDEN) ? j : (j + (P - HIDDEN));
        float v = 1.f / (1.f + expf(-__half2float(base[off])));
        p0 += v * Wc[j];
        p1 += v * Wc[2 * HIDDEN + j];
        p2 += v * Wc[4 * HIDDEN + j];
    }
#pragma unroll
    for (int o = 16; o; o >>= 1) {
        p0 += __shfl_down_sync(0xffffffffu, p0, o);
        p1 += __shfl_down_sync(0xffffffffu, p1, o);
        p2 += __shfl_down_sync(0xffffffffu, p2, o);
    }
    __shared__ float red[3][4];
    int warp = threadIdx.x >> 5, lane = threadIdx.x & 31;
    if (lane == 0) { red[0][warp] = p0; red[1][warp] = p1; red[2][warp] = p2; }
    __syncthreads();
    if (threadIdx.x == 0) {
        float l0 = bc[0], l1 = bc[1], l2 = bc[2];
        int nw = blockDim.x >> 5;
        for (int w = 0; w < nw; w++) { l0 += red[0][w]; l1 += red[1][w]; l2 += red[2][w]; }
        float m = fmaxf(l0, fmaxf(l1, l2));
        float s = expf(l0 - m) + expf(l1 - m) + expf(l2 - m);
        float lse = m + logf(s);
        out[b * 3 + 0] = l0 - lse;
        out[b * 3 + 1] = l1 - lse;
        out[b * 3 + 2] = l2 - lse;
    }
}

// ---------------- kernel_launch ----------------
extern "C" void kernel_launch(void* const* d_in, const int* in_sizes, int n_in,
                              void* d_out, int out_size) {
    const int*   word_ids  = (const int*)d_in[0];
    const float* embedding = (const float*)d_in[1];
    const float* W_leaf    = (const float*)d_in[2];
    const float* W_h       = (const float*)d_in[3];
    const float* b_h       = (const float*)d_in[4];
    const float* W_cls     = (const float*)d_in[5];
    const float* b_cls     = (const float*)d_in[6];
    float* out = (float*)d_out;

    __half *bufA, *bufB, *embH;
    uint32_t *bleaf, *bh;
    float *bias;
    cudaGetSymbolAddress((void**)&bufA, g_bufA);
    cudaGetSymbolAddress((void**)&bufB, g_bufB);
    cudaGetSymbolAddress((void**)&embH, g_embH);
    cudaGetSymbolAddress((void**)&bleaf, g_BleafP);
    cudaGetSymbolAddress((void**)&bh, g_BhP);
    cudaGetSymbolAddress((void**)&bias, g_bias);

    static bool attr_done = false;
    if (!attr_done) {
        cudaFuncSetAttribute(gemm_f16<true, false, 19, false>,
                             cudaFuncAttributeMaxDynamicSharedMemorySize, SMEM_TOT);
        cudaFuncSetAttribute(gemm_f16<false, true, 38, true>,
                             cudaFuncAttributeMaxDynamicSharedMemorySize, SMEM_TOT);
        attr_done = true;
    }

    prep_all<<<(PREP_TOT + 255) / 256, 256>>>(embedding, W_leaf, W_h, b_h);

    // leaf: H0[262144, 320] = fp16(emb[ids]) @ Bleaf  (K = 304, KT = 19)
    {
        dim3 grid(M0 / BM, 2);
        gemm_f16<true, false, 19, false><<<grid, 128, SMEM_TOT>>>(embH, word_ids, bleaf, nullptr,
                                                                  bufA, KP_LEAF);
    }

    // tree levels: view [2M, 320] as [M, 640]; KT = 38 (zero chunks skipped)
    __half* cur = bufA;
    int M = M0;
    for (int lvl = 0; lvl < 8; lvl++) {
        M >>= 1;
        __half* nxt = (cur == bufA) ? bufB : bufA;
        dim3 grid(M / BM, 2);
        gemm_f16<false, true, 38, true><<<grid, 128, SMEM_TOT>>>(cur, nullptr, bh, bias, nxt, KP_H);
        cur = nxt;
    }

    classifier_kernel<<<B_SZ, 128>>>(cur, W_cls, b_cls, out);
    (void)in_sizes; (void)n_in; (void)out_size;
}

// round 17
// speedup vs baseline: 2.0580x; 1.3385x over previous
#include <cuda_runtime.h>
#include <cuda_fp16.h>
#include <math.h>
#include <stdint.h>

// ---------------- problem constants ----------------
#define B_SZ    512
#define LEAVES  256
#define HIDDEN  300
#define VOCAB   50000
#define VPAD    50048                // vocab padded to multiple of 64
#define P       320                  // padded feature pitch (fp16 elements)
#define EPITCH  304                  // embedding fp16 pitch (608B, 16B-aligned)
#define M0      (B_SZ * 2 * LEAVES)  // 262144 leaf rows
#define M1      (M0 / 2)             // 131072 level-1 rows
#define KP_LEAF 304                  // 19 chunks
#define KP_H    640                  // 40 chunks (2 all-zero, skipped -> 38)

// ---------------- GEMM tiling (R12 exact) ----------------
#define BM     64
#define BN     160       // per-CTA N (2 CTAs cover 320)
#define BK     16
#define NSTAGE 6         // ring, prefetch distance 5
// compact layout: 32B row pitch (8 u32), XOR swizzle on 16B granule
#define ATILE_B   2048                   // 64 rows * 32B
#define BTILE_B   5120                   // 160 rows * 32B
#define CHUNK_U32 2560                   // full-320-row packed chunk (320*8 u32)
#define OFF_B_BASE (NSTAGE * ATILE_B)    // 12288
#define SMEM_TOT (NSTAGE * (ATILE_B + BTILE_B))   // 43008 B

// loader modes
#define MODE_PLAIN 0
#define MODE_GPAIR 2     // A row m = concat(Hw[ids[2m]], Hw[ids[2m+1]])

// ---------------- device scratch ----------------
__device__ __align__(16) __half g_bufA[(size_t)M1 * P];          // level ping
__device__ __align__(16) __half g_bufB[(size_t)(M1 / 2) * P];    // level pong
__device__ __align__(16) __half g_embH[(size_t)VPAD * EPITCH];
__device__ __align__(16) __half g_Hw[(size_t)VPAD * P];          // per-word leaf hidden
__device__ __align__(16) uint32_t g_BleafP[(KP_LEAF / BK) * CHUNK_U32];
__device__ __align__(16) uint32_t g_BhP[(KP_H / BK) * CHUNK_U32];
__device__ __align__(16) float g_bias[P];

// ---------------- PTX helpers ----------------
__device__ __forceinline__ uint32_t s2u(const void* p) {
    uint32_t a;
    asm("{.reg .u64 t; cvta.to.shared.u64 t, %1; cvt.u32.u64 %0, t;}" : "=r"(a) : "l"(p));
    return a;
}
__device__ __forceinline__ void cpa16(uint32_t dst, const void* src) {
    asm volatile("cp.async.cg.shared.global [%0], [%1], 16;\n" :: "r"(dst), "l"(src));
}
__device__ __forceinline__ void cpa_commit() { asm volatile("cp.async.commit_group;\n"); }
template <int N> __device__ __forceinline__ void cpa_wait() {
    asm volatile("cp.async.wait_group %0;\n" :: "n"(N));
}
__device__ __forceinline__ void ldsm4(uint32_t* r, uint32_t addr) {
    asm volatile("ldmatrix.sync.aligned.m8n8.x4.shared.b16 {%0,%1,%2,%3}, [%4];"
                 : "=r"(r[0]), "=r"(r[1]), "=r"(r[2]), "=r"(r[3]) : "r"(addr));
}
__device__ __forceinline__ void ldsm2(uint32_t* r, uint32_t addr) {
    asm volatile("ldmatrix.sync.aligned.m8n8.x2.shared.b16 {%0,%1}, [%2];"
                 : "=r"(r[0]), "=r"(r[1]) : "r"(addr));
}
__device__ __forceinline__ void mma_f16(float* d, const uint32_t* a, uint32_t b0, uint32_t b1) {
    asm volatile(
        "mma.sync.aligned.m16n8k16.row.col.f32.f16.f16.f32 "
        "{%0,%1,%2,%3}, {%4,%5,%6,%7}, {%8,%9}, {%0,%1,%2,%3};"
        : "+f"(d[0]), "+f"(d[1]), "+f"(d[2]), "+f"(d[3])
        : "r"(a[0]), "r"(a[1]), "r"(a[2]), "r"(a[3]), "r"(b0), "r"(b1));
}

// ---------------- merged prep kernel ----------------
#define NE_EMB  (VPAD * EPITCH)                // includes 48 pad rows (zeroed)
#define TL_LEAF ((KP_LEAF / BK) * CHUNK_U32)   // 48640
#define TL_TREE ((KP_H / BK) * CHUNK_U32)      // 102400
#define PREP_TOT (NE_EMB + TL_LEAF + TL_TREE + P)
__global__ void prep_all(const float* __restrict__ emb, const float* __restrict__ Wl,
                         const float* __restrict__ Wh, const float* __restrict__ bh) {
    int e = blockIdx.x * blockDim.x + threadIdx.x;
    if (e < NE_EMB) {
        int row = e / EPITCH, col = e % EPITCH;
        g_embH[e] = __float2half_rn((row < VOCAB && col < HIDDEN) ? emb[row * HIDDEN + col] : 0.f);
        return;
    }
    e -= NE_EMB;
    if (e < TL_LEAF) {
        int kt = e / CHUNK_U32, rme = e % CHUNK_U32;
        int n = rme >> 3, q = rme & 7;
        int g = (q >> 2) ^ ((n >> 2) & 1);
        int k = kt * BK + g * 8 + (q & 3) * 2;
        float v0 = 0.f, v1 = 0.f;
        if (n < HIDDEN && k < HIDDEN)     v0 = Wl[n * HIDDEN + k];
        if (n < HIDDEN && k + 1 < HIDDEN) v1 = Wl[n * HIDDEN + k + 1];
        __half2 h = __floats2half2_rn(v0, v1);
        g_BleafP[e] = *reinterpret_cast<uint32_t*>(&h);
        return;
    }
    e -= TL_LEAF;
    if (e < TL_TREE) {
        int kt = e / CHUNK_U32, rme = e % CHUNK_U32;
        int n = rme >> 3, q = rme & 7;
        int g = (q >> 2) ^ ((n >> 2) & 1);
        int kg = kt * BK + g * 8 + (q & 3) * 2;
        int half = (kg >= P) ? 1 : 0;
        int kk = kg - half * P;
        float v0 = 0.f, v1 = 0.f;
        if (n < HIDDEN && kk < HIDDEN)     v0 = Wh[n * (2 * HIDDEN) + half * HIDDEN + kk];
        if (n < HIDDEN && kk + 1 < HIDDEN) v1 = Wh[n * (2 * HIDDEN) + half * HIDDEN + kk + 1];
        __half2 h = __floats2half2_rn(v0, v1);
        g_BhP[e] = *reinterpret_cast<uint32_t*>(&h);
        return;
    }
    e -= TL_TREE;
    if (e < P) g_bias[e] = (e < HIDDEN) ? bh[e] : 0.f;
}

// ---------------- fp16 mma.sync GEMM (R12 structure + loader modes) --------
// grid = (M/64, 2); 128 thr; warp grid 1(M) x 4(N); warp tile 64 x 40.
// Per-chunk wait+barrier; LDFRAG(kt+1) issued before COMPUTE(kt) for overlap.
// MODE_PLAIN: A row m at pitch Kp.
// MODE_GPAIR: A row m = concat(Hw[ids[2m]](320 pitch), Hw[ids[2m+1]]);
//             chunk index (compile-time) selects the half -> folds to 2 ptrs.
template <int MODE, bool BIAS, int KT, bool SKIP>
__global__ __launch_bounds__(128, 3)
void gemm_f16(const __half* __restrict__ A, const int* __restrict__ ids,
              const uint32_t* __restrict__ Bp, const float* __restrict__ bias,
              __half* __restrict__ C, int Kp) {
    extern __shared__ uint32_t smem[];
    const uint32_t sb = s2u(smem);
    const int t = threadIdx.x;
    const int wid = t >> 5, lane = t & 31;
    const int m0 = blockIdx.x * BM;
    const int nb = blockIdx.y * BN;

    // A loader: row lm = t>>1, granule lg = t&1 (16B), swizzled store
    const int lm = t >> 1, lg = t & 1;
    const __half* arow;
    const __half* arow2 = nullptr;
    if (MODE == MODE_GPAIR) {
        int m = m0 + lm;
        arow  = A + (size_t)ids[2 * m]     * P;
        arow2 = A + (size_t)ids[2 * m + 1] * P;
    } else {
        arow = A + (size_t)(m0 + lm) * Kp;
    }
    const uint32_t aDstOff = (uint32_t)(lm * 32 + ((lg ^ ((lm >> 2) & 1)) << 4));

    const uint32_t bDstBase = sb + OFF_B_BASE;
    const uint32_t bSrcRow  = (uint32_t)nb * 8;

    const int l = lane;
    const int rowA = (l & 7) + ((l >> 3) & 1) * 8;
    const uint32_t laneoffA = (uint32_t)(rowA * 32 + ((((l >> 4) & 1) ^ ((rowA >> 2) & 1)) << 4));
    const int rowB = (l & 7) + ((l >> 4) & 1) * 8;
    const uint32_t laneoffB = (uint32_t)(rowB * 32 + ((((l >> 3) & 1) ^ ((rowB >> 2) & 1)) << 4));
    const int rowB2 = l & 7;
    const uint32_t laneoffB2 = (uint32_t)(rowB2 * 32 + ((((l >> 3) & 1) ^ ((rowB2 >> 2) & 1)) << 4));
    const uint32_t wB = (uint32_t)(wid * 40 * 32);

    float acc[4][5][4];
#pragma unroll
    for (int mt = 0; mt < 4; mt++)
#pragma unroll
        for (int nt = 0; nt < 5; nt++)
#pragma unroll
            for (int q = 0; q < 4; q++) acc[mt][nt][q] = 0.f;

    uint32_t fa[2][4][4], fb[2][10];

#define MAPKT(kt)  (SKIP ? ((kt) + ((kt) >= 19)) : (kt))
#define ASRC(ktm)  ((MODE == MODE_GPAIR)                                          \
                        ? (((ktm) < 20) ? (arow + (ktm) * BK)                     \
                                        : (arow2 + ((ktm) - 20) * BK))            \
                        : (arow + (ktm) * BK))
#define LOAD_AB(s, ktm)                                                          \
    do {                                                                         \
        cpa16(sb + (s) * ATILE_B + aDstOff, ASRC(ktm) + lg * 8);                 \
        const uint32_t* _bsrc = Bp + (size_t)(ktm) * CHUNK_U32 + bSrcRow;        \
        uint32_t _bdst = bDstBase + (s) * BTILE_B;                               \
        cpa16(_bdst + t * 16, _bsrc + t * 4);                                    \
        cpa16(_bdst + (t + 128) * 16, _bsrc + (t + 128) * 4);                    \
        if (t < 64) cpa16(_bdst + (t + 256) * 16, _bsrc + (t + 256) * 4);        \
    } while (0)
#define LDFRAG(buf, s)                                                           \
    do {                                                                         \
        const uint32_t _sA = sb + (s) * ATILE_B;                                 \
        const uint32_t _sB = bDstBase + (s) * BTILE_B + wB;                      \
        ldsm4(fa[buf][0], _sA + 0 * 512 + laneoffA);                             \
        ldsm4(fa[buf][1], _sA + 1 * 512 + laneoffA);                             \
        ldsm4(fa[buf][2], _sA + 2 * 512 + laneoffA);                             \
        ldsm4(fa[buf][3], _sA + 3 * 512 + laneoffA);                             \
        ldsm4(&fb[buf][0], _sB + laneoffB);                                      \
        ldsm4(&fb[buf][4], _sB + 512 + laneoffB);                                \
        ldsm2(&fb[buf][8], _sB + 1024 + laneoffB2);                              \
    } while (0)
#define COMPUTE(buf)                                                             \
    do {                                                                         \
        _Pragma("unroll")                                                        \
        for (int mt = 0; mt < 4; mt++) {                                         \
            mma_f16(acc[mt][0], fa[buf][mt], fb[buf][0], fb[buf][1]);            \
            mma_f16(acc[mt][1], fa[buf][mt], fb[buf][2], fb[buf][3]);            \
            mma_f16(acc[mt][2], fa[buf][mt], fb[buf][4], fb[buf][5]);            \
            mma_f16(acc[mt][3], fa[buf][mt], fb[buf][6], fb[buf][7]);            \
            mma_f16(acc[mt][4], fa[buf][mt], fb[buf][8], fb[buf][9]);            \
        }                                                                        \
    } while (0)

    // prologue: fill 5 stages (chunks 0..4)
#pragma unroll
    for (int s = 0; s < 5; s++) { LOAD_AB(s, MAPKT(s)); cpa_commit(); }

    cpa_wait<3>();   // chunks 0,1 resident
    __syncthreads();
    LDFRAG(0, 0);    // chunk 0 -> buffer 0

    // main loop: one wait+barrier per chunk; LDFRAG(kt+1) before COMPUTE(kt)
#pragma unroll
    for (int kt = 0; kt < KT; kt++) {
        const int cur = kt & 1, nxt = cur ^ 1;
        if (kt + 5 < KT) { LOAD_AB((kt + 5) % NSTAGE, MAPKT(kt + 5)); }
        cpa_commit();
        if (kt + 1 < KT) {
            cpa_wait<3>();      // chunk kt+1 resident
            __syncthreads();    // visibility + stage-reuse ordering
            LDFRAG(nxt, (kt + 1) % NSTAGE);
        }
        COMPUTE(cur);
    }

    // epilogue
    const int r = lane >> 2, c = lane & 3;
#pragma unroll
    for (int mt = 0; mt < 4; mt++) {
        int row = m0 + mt * 16 + r;
#pragma unroll
        for (int nt = 0; nt < 5; nt++) {
            int col = nb + wid * 40 + nt * 8 + 2 * c;
            float v0 = acc[mt][nt][0], v1 = acc[mt][nt][1];
            float v2 = acc[mt][nt][2], v3 = acc[mt][nt][3];
            if (BIAS) {
                float b0 = __ldg(bias + col), b1 = __ldg(bias + col + 1);
                v0 += b0; v1 += b1; v2 += b0; v3 += b1;
            }
            __half2 h0 = __floats2half2_rn(v0, v1);
            __half2 h1 = __floats2half2_rn(v2, v3);
            *reinterpret_cast<__half2*>(&C[(size_t)row * P + col])       = h0;
            *reinterpret_cast<__half2*>(&C[(size_t)(row + 8) * P + col]) = h1;
        }
    }
#undef MAPKT
#undef ASRC
#undef LOAD_AB
#undef LDFRAG
#undef COMPUTE
}

// ---------------- classifier ----------------
__global__ void classifier_kernel(const __half* __restrict__ roots,
                                  const float* __restrict__ Wc,
                                  const float* __restrict__ bc,
                                  float* __restrict__ out) {
    const int b = blockIdx.x;
    const __half* base = roots + (size_t)(2 * b) * P;
    float p0 = 0.f, p1 = 0.f, p2 = 0.f;
    for (int j = threadIdx.x; j < 2 * HIDDEN; j += blockDim.x) {
        int off = (j < HIDDEN) ? j : (j + (P - HIDDEN));
        float v = 1.f / (1.f + expf(-__half2float(base[off])));
        p0 += v * Wc[j];
        p1 += v * Wc[2 * HIDDEN + j];
        p2 += v * Wc[4 * HIDDEN + j];
    }
#pragma unroll
    for (int o = 16; o; o >>= 1) {
        p0 += __shfl_down_sync(0xffffffffu, p0, o);
        p1 += __shfl_down_sync(0xffffffffu, p1, o);
        p2 += __shfl_down_sync(0xffffffffu, p2, o);
    }
    __shared__ float red[3][4];
    int warp = threadIdx.x >> 5, lane = threadIdx.x & 31;
    if (lane == 0) { red[0][warp] = p0; red[1][warp] = p1; red[2][warp] = p2; }
    __syncthreads();
    if (threadIdx.x == 0) {
        float l0 = bc[0], l1 = bc[1], l2 = bc[2];
        int nw = blockDim.x >> 5;
        for (int w = 0; w < nw; w++) { l0 += red[0][w]; l1 += red[1][w]; l2 += red[2][w]; }
        float m = fmaxf(l0, fmaxf(l1, l2));
        float s = expf(l0 - m) + expf(l1 - m) + expf(l2 - m);
        float lse = m + logf(s);
        out[b * 3 + 0] = l0 - lse;
        out[b * 3 + 1] = l1 - lse;
        out[b * 3 + 2] = l2 - lse;
    }
}

// ---------------- kernel_launch ----------------
extern "C" void kernel_launch(void* const* d_in, const int* in_sizes, int n_in,
                              void* d_out, int out_size) {
    const int*   word_ids  = (const int*)d_in[0];
    const float* embedding = (const float*)d_in[1];
    const float* W_leaf    = (const float*)d_in[2];
    const float* W_h       = (const float*)d_in[3];
    const float* b_h       = (const float*)d_in[4];
    const float* W_cls     = (const float*)d_in[5];
    const float* b_cls     = (const float*)d_in[6];
    float* out = (float*)d_out;

    __half *bufA, *bufB, *embH, *hw;
    uint32_t *bleaf, *bh;
    float *bias;
    cudaGetSymbolAddress((void**)&bufA, g_bufA);
    cudaGetSymbolAddress((void**)&bufB, g_bufB);
    cudaGetSymbolAddress((void**)&embH, g_embH);
    cudaGetSymbolAddress((void**)&hw, g_Hw);
    cudaGetSymbolAddress((void**)&bleaf, g_BleafP);
    cudaGetSymbolAddress((void**)&bh, g_BhP);
    cudaGetSymbolAddress((void**)&bias, g_bias);

    static bool attr_done = false;
    if (!attr_done) {
        cudaFuncSetAttribute(gemm_f16<MODE_PLAIN, false, 19, false>,
                             cudaFuncAttributeMaxDynamicSharedMemorySize, SMEM_TOT);
        cudaFuncSetAttribute(gemm_f16<MODE_GPAIR, true, 38, true>,
                             cudaFuncAttributeMaxDynamicSharedMemorySize, SMEM_TOT);
        cudaFuncSetAttribute(gemm_f16<MODE_PLAIN, true, 38, true>,
                             cudaFuncAttributeMaxDynamicSharedMemorySize, SMEM_TOT);
        attr_done = true;
    }

    prep_all<<<(PREP_TOT + 255) / 256, 256>>>(embedding, W_leaf, W_h, b_h);

    // per-word leaf hidden: Hw[50048, 320] = fp16(embH) @ Bleaf  (K=304, KT=19)
    {
        dim3 grid(VPAD / BM, 2);
        gemm_f16<MODE_PLAIN, false, 19, false><<<grid, 128, SMEM_TOT>>>(
            embH, nullptr, bleaf, nullptr, hw, KP_LEAF);
    }

    // tree level 1 (fused gather): A row m = concat(Hw[ids[2m]], Hw[ids[2m+1]])
    {
        dim3 grid(M1 / BM, 2);
        gemm_f16<MODE_GPAIR, true, 38, true><<<grid, 128, SMEM_TOT>>>(
            hw, word_ids, bh, bias, bufA, KP_H);
    }

    // tree levels 2..8: view [2M, 320] as [M, 640]; KT = 38 (zero chunks skipped)
    __half* cur = bufA;
    int M = M1;
    for (int lvl = 1; lvl < 8; lvl++) {
        M >>= 1;
        __half* nxt = (cur == bufA) ? bufB : bufA;
        dim3 grid(M / BM, 2);
        gemm_f16<MODE_PLAIN, true, 38, true><<<grid, 128, SMEM_TOT>>>(
            cur, nullptr, bh, bias, nxt, KP_H);
        cur = nxt;
    }

    classifier_kernel<<<B_SZ, 128>>>(cur, W_cls, b_cls, out);
    (void)in_sizes; (void)n_in; (void)out_size;
}